// round 16
// baseline (speedup 1.0000x reference)
#include <cuda_runtime.h>
#include <cuda_fp16.h>
#include <cstdint>

#define NEGV (-1e30f)

// ============================ scratch (no allocs) ============================
__device__ __half   g_Xh[33554432];                     // X fp16
__device__ __half   g_Yh[33554432];                     // Y fp16
__device__ __half   g_Kh[33554432];                     // K fp16 [b][t][h]
__device__ __half   g_Qh[33554432];                     // Q fp16 [b][t][h]
__device__ __half   g_Vth[33554432];                    // V^T fp16 [b][h][t]
__device__ __half   g_Ph[67108864];                     // E, then P (in place)
__device__ __half   g_Wth[786432];                      // 3x W^T [h][d] fp16
__device__ uint8_t  g_dagU8[1048576];                   // dag^T u8 [t][s]
__device__ float    g_mxt[524288];                      // per-(row,tile) max
__device__ float    g_rst[524288];                      // per-(row,tile) sum
__device__ float    g_f  [524288];                      // per-(row,tile) scale

// ============================ PTX helpers (base sm_103 ISA) ==================
__device__ __forceinline__ uint32_t smem_u32(const void* p) {
    uint32_t a;
    asm("{ .reg .u64 t; cvta.to.shared.u64 t, %1; cvt.u32.u64 %0, t; }" : "=r"(a) : "l"(p));
    return a;
}
#define CP_ASYNC16(dst, src) \
    asm volatile("cp.async.cg.shared.global [%0], [%1], 16;" :: "r"(dst), "l"(src))
#define CP_COMMIT() asm volatile("cp.async.commit_group;" ::: "memory")
#define CP_WAIT(n)  asm volatile("cp.async.wait_group %0;" :: "n"(n) : "memory")

__device__ __forceinline__ void ldsm_x4(uint32_t& r0, uint32_t& r1, uint32_t& r2, uint32_t& r3,
                                        uint32_t addr) {
    asm volatile("ldmatrix.sync.aligned.m8n8.x4.shared.b16 {%0,%1,%2,%3}, [%4];"
                 : "=r"(r0), "=r"(r1), "=r"(r2), "=r"(r3) : "r"(addr));
}
__device__ __forceinline__ void mma_f16(float* c, const uint32_t* a, uint32_t b0, uint32_t b1) {
    asm volatile(
        "mma.sync.aligned.m16n8k16.row.col.f32.f16.f16.f32 "
        "{%0,%1,%2,%3}, {%4,%5,%6,%7}, {%8,%9}, {%0,%1,%2,%3};"
        : "+f"(c[0]), "+f"(c[1]), "+f"(c[2]), "+f"(c[3])
        : "r"(a[0]), "r"(a[1]), "r"(a[2]), "r"(a[3]), "r"(b0), "r"(b1));
}
#define SWZ128(o) ((o) ^ (((o) >> 3) & 0x70))

__device__ __forceinline__ uint32_t pack2h(float a, float b) {
    return (uint32_t)__half_as_ushort(__float2half_rn(a)) |
           ((uint32_t)__half_as_ushort(__float2half_rn(b)) << 16);
}

static constexpr int STAGE_BYTES = 32768;             // A 16KB + B 16KB
static constexpr int SMEM_BYTES  = 2 * STAGE_BYTES;   // 64KB -> 3 CTAs/SM

// ============================ shared GEMM mainloop ===========================
// 128 threads / 4 warps as 2(M) x 2(N); warp tile 64x64; CTA tile 128x128.
// 2-stage cp.async: wait(0) -> barrier -> prefetch(i+1) -> compute(i).
__device__ __forceinline__ void gemm_mainloop(
    float (&acc)[4][8][4], uint32_t sb,
    const __half* __restrict__ srcA, int lda,
    const __half* __restrict__ srcB, int ldb, int nch)
{
    const int tid = threadIdx.x, wid = tid >> 5, lane = tid & 31;
    const int warpM = (wid >> 1) * 64, warpN = (wid & 1) * 64;
    const int aRow  = warpM + (lane & 15);
    const int bRow  = warpN + (lane & 15);
    const int kHalf = (lane >> 4) * 8;

    auto load_stage = [&](int st, int k0) {
        const uint32_t stBase = sb + st * STAGE_BYTES;
#pragma unroll
        for (int i = 0; i < 8; i++) {
            const int idx = (i << 7) | tid;
            const int row = idx >> 3, k8 = (idx & 7) << 3;
            CP_ASYNC16(stBase + SWZ128((uint32_t)(row * 128 + k8 * 2)),
                       srcA + (long long)row * lda + k0 + k8);
        }
#pragma unroll
        for (int i = 0; i < 8; i++) {
            const int idx = (i << 7) | tid;
            const int row = idx >> 3, k8 = (idx & 7) << 3;
            CP_ASYNC16(stBase + 16384 + SWZ128((uint32_t)(row * 128 + k8 * 2)),
                       srcB + (long long)row * ldb + k0 + k8);
        }
    };

#pragma unroll
    for (int mi = 0; mi < 4; mi++)
#pragma unroll
        for (int ni = 0; ni < 8; ni++)
#pragma unroll
            for (int c = 0; c < 4; c++) acc[mi][ni][c] = 0.0f;

    load_stage(0, 0);
    CP_COMMIT();

    for (int i = 0; i < nch; i++) {
        const int st = i & 1;
        CP_WAIT(0);
        __syncthreads();
        if (i + 1 < nch) { load_stage(st ^ 1, (i + 1) << 6); CP_COMMIT(); }

        const uint32_t aB = sb + st * STAGE_BYTES;
        const uint32_t bB = aB + 16384;
#pragma unroll
        for (int ks = 0; ks < 4; ks++) {
            const int kb = (ks * 16 + kHalf) * 2;
            uint32_t bf[8][2];
#pragma unroll
            for (int np = 0; np < 4; np++) {
                uint32_t r0, r1, r2, r3;
                ldsm_x4(r0, r1, r2, r3, bB + SWZ128((uint32_t)((bRow + np * 16) * 128 + kb)));
                bf[np * 2 + 0][0] = r0; bf[np * 2 + 0][1] = r2;
                bf[np * 2 + 1][0] = r1; bf[np * 2 + 1][1] = r3;
            }
            uint32_t af[4][4];
#pragma unroll
            for (int mi = 0; mi < 4; mi++)
                ldsm_x4(af[mi][0], af[mi][1], af[mi][2], af[mi][3],
                        aB + SWZ128((uint32_t)((aRow + mi * 16) * 128 + kb)));
#pragma unroll
            for (int mi = 0; mi < 4; mi++)
#pragma unroll
                for (int ni = 0; ni < 8; ni++)
                    mma_f16(acc[mi][ni], af[mi], bf[ni][0], bf[ni][1]);
        }
    }
}

// ============================ prep kernels ===================================
__global__ __launch_bounds__(256) void halfXY_kernel(const float4* __restrict__ X,
                                                     const float4* __restrict__ Y) {
    int i = blockIdx.x * 256 + threadIdx.x;
    const float4* s; uint2* d; int j;
    if (i < 8388608) { s = X; d = (uint2*)g_Xh; j = i; }
    else             { s = Y; d = (uint2*)g_Yh; j = i - 8388608; }
    float4 v = s[j];
    uint2 hh;
    hh.x = pack2h(v.x, v.y);
    hh.y = pack2h(v.z, v.w);
    d[j] = hh;
}

__global__ __launch_bounds__(256) void prep2_kernel(const float* __restrict__ Wk,
                                                    const float* __restrict__ Wq,
                                                    const float* __restrict__ Wv,
                                                    const float* __restrict__ dag) {
    int i = blockIdx.x * 256 + threadIdx.x;
    if (i < 786432) {
        int z = i >> 18, r = i & 262143;
        const float* W = (z == 0) ? Wk : (z == 1) ? Wq : Wv;
        int hh = r >> 9, d = r & 511;
        g_Wth[i] = __float2half_rn(W[d * 512 + hh]);
    } else {
        int j = i - 786432;
        int t = j >> 10, s = j & 1023;
        g_dagU8[j] = (dag[s * 1024 + t] != 0.0f) ? 1 : 0;
    }
}

// ============================ projections (one launch) =======================
// grid (4, 512, 3): z=0 K (row-major), z=1 Q (row-major), z=2 V^T (transposed)
__global__ __launch_bounds__(128, 3) void proj_kernel(const float* __restrict__ bk,
                                                      const float* __restrict__ bq,
                                                      const float* __restrict__ bv)
{
    extern __shared__ char smem[];
    const int z = blockIdx.z;
    const __half* A = (z == 1) ? g_Yh : g_Xh;
    const __half* W = g_Wth + z * 262144;
    const float* bias = (z == 0) ? bk : (z == 1) ? bq : bv;
    __half* out = (z == 0) ? g_Kh : (z == 1) ? g_Qh : g_Vth;

    const int mBase = blockIdx.y * 128;
    const int nBase = blockIdx.x * 128;
    const int tid = threadIdx.x, wid = tid >> 5, lane = tid & 31;
    const int warpM = (wid >> 1) * 64, warpN = (wid & 1) * 64;
    const uint32_t sb = smem_u32(smem);

    float acc[4][8][4];
    gemm_mainloop(acc, sb, A + (long long)mBase * 512, 512,
                  W + (long long)nBase * 512, 512, 8);

    const int rBase = lane >> 2;
    const int cOff  = (lane & 3) * 2;

    if (z != 2) {
        // direct row-major fp16 stores (uint32 = 2 halves per lane)
#pragma unroll
        for (int mi = 0; mi < 4; mi++)
#pragma unroll
            for (int ni = 0; ni < 8; ni++)
#pragma unroll
                for (int rh = 0; rh < 2; rh++) {
                    const int row = mBase + warpM + mi * 16 + rBase + rh * 8;
                    const int col = nBase + warpN + ni * 8 + cOff;
                    const float b0 = bias[col], b1 = bias[col + 1];
                    *(uint32_t*)(out + (long long)row * 512 + col) =
                        pack2h(acc[mi][ni][rh * 2] + b0, acc[mi][ni][rh * 2 + 1] + b1);
                }
    } else {
        // transposed output: stage 64-column halves (ownership = warpN)
        __syncthreads();
        uint32_t* stgU = (uint32_t*)smem;   // 64 cols x 132 rows-slots (33KB)
#pragma unroll
        for (int chalf = 0; chalf < 2; chalf++) {
            const int clo = chalf * 64;
            if (warpN == clo) {
#pragma unroll
                for (int mi = 0; mi < 4; mi++) {
                    const int r0 = warpM + mi * 16 + rBase;
                    const int r1 = r0 + 8;
#pragma unroll
                    for (int ni = 0; ni < 8; ni++) {
                        const int colL = ni * 8 + cOff;          // 0..63 within half
                        const int col = nBase + clo + colL;
                        const float b0 = bias[col], b1 = bias[col + 1];
                        stgU[colL * 132 + r0]       = (uint32_t)__half_as_ushort(__float2half_rn(acc[mi][ni][0] + b0));
                        stgU[(colL + 1) * 132 + r0] = (uint32_t)__half_as_ushort(__float2half_rn(acc[mi][ni][1] + b1));
                        stgU[colL * 132 + r1]       = (uint32_t)__half_as_ushort(__float2half_rn(acc[mi][ni][2] + b0));
                        stgU[(colL + 1) * 132 + r1] = (uint32_t)__half_as_ushort(__float2half_rn(acc[mi][ni][3] + b1));
                    }
                }
            }
            __syncthreads();
            // copy out 64 cols x 128 rows (4 rows per thread-step, uint2 = 4 halves)
#pragma unroll
            for (int i = 0; i < 16; i++) {
                const int q = tid + i * 128;
                const int c = q >> 5, r4 = (q & 31) << 2;
                uint32_t w0 = stgU[c * 132 + r4], w1 = stgU[c * 132 + r4 + 1];
                uint32_t w2 = stgU[c * 132 + r4 + 2], w3 = stgU[c * 132 + r4 + 3];
                uint2 hh;
                hh.x = (w0 & 0xFFFF) | (w1 << 16);  hh.y = (w2 & 0xFFFF) | (w3 << 16);
                const int gt = mBase + r4;
                const int bat = gt >> 10, t0 = gt & 1023;
                const long long gi = ((long long)bat * 512 + (nBase + clo + c)) * 1024 + t0;
                *(uint2*)(out + gi) = hh;
            }
            __syncthreads();
        }
    }
}

// ============================ scores + tile softmax ==========================
// grid (8, 8, 64), 128 thr. Direct E stores; per-(row,tile) stats for factor.
__global__ __launch_bounds__(128, 3) void scores_kernel()
{
    extern __shared__ char smem[];
    const int b = blockIdx.z;
    const int mBase = blockIdx.y * 128;     // t rows
    const int nBase = blockIdx.x * 128;     // s cols (tile = blockIdx.x)
    const int tid = threadIdx.x, wid = tid >> 5, lane = tid & 31;
    const int warpM = (wid >> 1) * 64, warpN = (wid & 1) * 64;
    const int ngrp = wid & 1;
    const uint32_t sb = smem_u32(smem);

    float acc[4][8][4];
    gemm_mainloop(acc, sb,
                  g_Qh + (long long)b * 524288 + (long long)mBase * 512, 512,
                  g_Kh + (long long)b * 524288 + (long long)nBase * 512, 512, 8);

    __syncthreads();                              // stages free for stats
    float* sm_mx = (float*)smem;                  // [2][128]
    float* sm_rs = (float*)(smem + 1024);         // [2][128]

    const int rBase = lane >> 2;
    const int cOff  = (lane & 3) * 2;
    const float scale = 0.044194173824159216f;    // 1/sqrt(512)

    float rmax[4][2];
#pragma unroll
    for (int mi = 0; mi < 4; mi++) { rmax[mi][0] = NEGV; rmax[mi][1] = NEGV; }
#pragma unroll
    for (int mi = 0; mi < 4; mi++)
#pragma unroll
        for (int ni = 0; ni < 8; ni++)
#pragma unroll
            for (int rh = 0; rh < 2; rh++) {
                const int t = mBase + warpM + mi * 16 + rBase + rh * 8;
                const int s = nBase + warpN + ni * 8 + cOff;
                const uint16_t dg = *(const uint16_t*)(g_dagU8 + (long long)t * 1024 + s);
                float v0 = acc[mi][ni][rh * 2]     * scale;
                float v1 = acc[mi][ni][rh * 2 + 1] * scale;
                v0 = ((dg & 0xFF) && v0 != 0.0f) ? v0 : NEGV;
                v1 = ((dg >> 8)  && v1 != 0.0f) ? v1 : NEGV;
                acc[mi][ni][rh * 2]     = v0;
                acc[mi][ni][rh * 2 + 1] = v1;
                rmax[mi][rh] = fmaxf(rmax[mi][rh], fmaxf(v0, v1));
            }
#pragma unroll
    for (int mi = 0; mi < 4; mi++)
#pragma unroll
        for (int rh = 0; rh < 2; rh++) {
            float v = rmax[mi][rh];
            v = fmaxf(v, __shfl_xor_sync(0xffffffffu, v, 1));
            v = fmaxf(v, __shfl_xor_sync(0xffffffffu, v, 2));
            if ((lane & 3) == 0)
                sm_mx[ngrp * 128 + warpM + mi * 16 + rBase + rh * 8] = v;
        }
    __syncthreads();

    // e = exp(lg - mx_tile), row sums, DIRECT fp16 stores
    float rsum[4][2] = {{0.f,0.f},{0.f,0.f},{0.f,0.f},{0.f,0.f}};
#pragma unroll
    for (int mi = 0; mi < 4; mi++)
#pragma unroll
        for (int rh = 0; rh < 2; rh++) {
            const int row = warpM + mi * 16 + rBase + rh * 8;
            const float mxt = fmaxf(sm_mx[row], sm_mx[128 + row]);
            const long long gbase = ((long long)b * 1024 + mBase + row) * 1024 + nBase;
#pragma unroll
            for (int ni = 0; ni < 8; ni++) {
                const int col = warpN + ni * 8 + cOff;
                float l0 = acc[mi][ni][rh * 2], l1 = acc[mi][ni][rh * 2 + 1];
                float e0 = (l0 < -1e29f) ? 0.0f : __expf(l0 - mxt);
                float e1 = (l1 < -1e29f) ? 0.0f : __expf(l1 - mxt);
                rsum[mi][rh] += e0 + e1;
                *(uint32_t*)(g_Ph + gbase + col) = pack2h(e0, e1);
            }
        }
#pragma unroll
    for (int mi = 0; mi < 4; mi++)
#pragma unroll
        for (int rh = 0; rh < 2; rh++) {
            float v = rsum[mi][rh];
            v += __shfl_xor_sync(0xffffffffu, v, 1);
            v += __shfl_xor_sync(0xffffffffu, v, 2);
            if ((lane & 3) == 0)
                sm_rs[ngrp * 128 + warpM + mi * 16 + rBase + rh * 8] = v;
        }
    __syncthreads();

    if (tid < 128) {
        const long long r = (long long)b * 1024 + mBase + tid;
        g_mxt[r * 8 + blockIdx.x] = fmaxf(sm_mx[tid], sm_mx[128 + tid]);
        g_rst[r * 8 + blockIdx.x] = sm_rs[tid] + sm_rs[128 + tid];
    }
}

// ============================ factor + scale =================================
__global__ __launch_bounds__(256) void factor_kernel() {
    const int r = blockIdx.x * 256 + threadIdx.x;
    float mx8[8], rs8[8];
#pragma unroll
    for (int j = 0; j < 8; j++) { mx8[j] = g_mxt[r * 8 + j]; rs8[j] = g_rst[r * 8 + j]; }
    float mx = mx8[0];
#pragma unroll
    for (int j = 1; j < 8; j++) mx = fmaxf(mx, mx8[j]);
    if (mx < -1e29f) {
#pragma unroll
        for (int j = 0; j < 8; j++) g_f[r * 8 + j] = 0.0f;
        return;
    }
    float l = 0.0f, a8[8];
#pragma unroll
    for (int j = 0; j < 8; j++) {
        a8[j] = (mx8[j] < -1e29f) ? 0.0f : __expf(mx8[j] - mx);
        l += rs8[j] * a8[j];
    }
    const float inv = 1.0f / l;
#pragma unroll
    for (int j = 0; j < 8; j++) g_f[r * 8 + j] = a8[j] * inv;
}

__global__ __launch_bounds__(256) void scale_kernel() {
    const int i = blockIdx.x * 256 + threadIdx.x;
    const int row = i >> 7;
    const int ti  = (i >> 4) & 7;
    const float f = g_f[row * 8 + ti];
    uint4* P = (uint4*)g_Ph;
    uint4 v = P[i];
    auto sc = [&](uint32_t w) -> uint32_t {
        float a = __half2float(__ushort_as_half((unsigned short)(w & 0xFFFF))) * f;
        float b = __half2float(__ushort_as_half((unsigned short)(w >> 16))) * f;
        return pack2h(a, b);
    };
    v.x = sc(v.x); v.y = sc(v.y); v.z = sc(v.z); v.w = sc(v.w);
    P[i] = v;
}

// ============================ A@V output =====================================
__global__ __launch_bounds__(128, 3) void av_kernel(float* __restrict__ O)
{
    extern __shared__ char smem[];
    const int b = blockIdx.z;
    const int mBase = blockIdx.y * 128;
    const int nBase = blockIdx.x * 128;
    const int tid = threadIdx.x, wid = tid >> 5, lane = tid & 31;
    const int warpM = (wid >> 1) * 64, warpN = (wid & 1) * 64;
    const uint32_t sb = smem_u32(smem);

    float acc[4][8][4];
    gemm_mainloop(acc, sb,
                  g_Ph  + (long long)b * 1048576 + (long long)mBase * 1024, 1024,
                  g_Vth + (long long)b * 524288  + (long long)nBase * 1024, 1024, 16);

    const int rBase = lane >> 2;
    const int cOff  = (lane & 3) * 2;
#pragma unroll
    for (int mi = 0; mi < 4; mi++)
#pragma unroll
        for (int ni = 0; ni < 8; ni++)
#pragma unroll
            for (int rh = 0; rh < 2; rh++) {
                const int row = mBase + warpM + mi * 16 + rBase + rh * 8;
                const int col = nBase + warpN + ni * 8 + cOff;
                float2 o;
                o.x = acc[mi][ni][rh * 2];
                o.y = acc[mi][ni][rh * 2 + 1];
                *(float2*)(O + (long long)b * 524288 + (long long)row * 512 + col) = o;
            }
}

// ============================ launch =========================================
extern "C" void kernel_launch(void* const* d_in, const int* in_sizes, int n_in,
                              void* d_out, int out_size)
{
    const float* X   = (const float*)d_in[0];
    const float* Y   = (const float*)d_in[1];
    const float* dag = (const float*)d_in[2];
    const float* Wk  = (const float*)d_in[3];
    const float* bk  = (const float*)d_in[4];
    const float* Wq  = (const float*)d_in[5];
    const float* bq  = (const float*)d_in[6];
    const float* Wv  = (const float*)d_in[7];
    const float* bv  = (const float*)d_in[8];
    float* O = (float*)d_out;

    cudaFuncSetAttribute(proj_kernel,   cudaFuncAttributeMaxDynamicSharedMemorySize, SMEM_BYTES);
    cudaFuncSetAttribute(scores_kernel, cudaFuncAttributeMaxDynamicSharedMemorySize, SMEM_BYTES);
    cudaFuncSetAttribute(av_kernel,     cudaFuncAttributeMaxDynamicSharedMemorySize, SMEM_BYTES);

    dim3 blk256(256), blk128(128);

    // prep
    halfXY_kernel<<<65536, blk256>>>((const float4*)X, (const float4*)Y);
    prep2_kernel<<<7168, blk256>>>(Wk, Wq, Wv, dag);

    // projections (K, Q, V^T) in one launch; 128x128 tiles, 128-thr CTAs
    dim3 gproj(4, 512, 3);
    proj_kernel<<<gproj, blk128, SMEM_BYTES>>>(bk, bq, bv);

    // scores + tile-local softmax pieces
    dim3 gsc(8, 8, 64);
    scores_kernel<<<gsc, blk128, SMEM_BYTES>>>();

    // combine stats -> per-tile scales; normalize E -> P (in place)
    factor_kernel<<<256, blk256>>>();
    scale_kernel<<<32768, blk256>>>();

    // output GEMM
    dim3 gav(4, 8, 64);
    av_kernel<<<gav, blk128, SMEM_BYTES>>>(O);
}

// round 17
// speedup vs baseline: 1.2244x; 1.2244x over previous
#include <cuda_runtime.h>
#include <cuda_fp16.h>
#include <cstdint>

#define NEGV (-1e30f)

// ============================ scratch (no allocs) ============================
__device__ __half   g_Xh[33554432];                     // X fp16
__device__ __half   g_Yh[33554432];                     // Y fp16
__device__ __half   g_Kh[33554432];                     // K fp16 [b][t][h]
__device__ __half   g_Qh[33554432];                     // Q fp16 [b][t][h]
__device__ __half   g_Vth[33554432];                    // V^T fp16 [b][h][t]
__device__ __half   g_Ph[67108864];                     // E, then P (in place)
__device__ __half   g_Wth[786432];                      // 3x W^T [h][d] fp16
__device__ uint8_t  g_dagU8[1048576];                   // dag^T u8 [t][s]
__device__ float    g_mxt[524288];                      // per-(row,tile) max
__device__ float    g_rst[524288];                      // per-(row,tile) sum
__device__ float    g_f  [524288];                      // per-(row,tile) scale

// ============================ PTX helpers (base sm_103 ISA) ==================
__device__ __forceinline__ uint32_t smem_u32(const void* p) {
    uint32_t a;
    asm("{ .reg .u64 t; cvta.to.shared.u64 t, %1; cvt.u32.u64 %0, t; }" : "=r"(a) : "l"(p));
    return a;
}
#define CP_ASYNC16(dst, src) \
    asm volatile("cp.async.cg.shared.global [%0], [%1], 16;" :: "r"(dst), "l"(src))
#define CP_COMMIT() asm volatile("cp.async.commit_group;" ::: "memory")
#define CP_WAIT(n)  asm volatile("cp.async.wait_group %0;" :: "n"(n) : "memory")

__device__ __forceinline__ void ldsm_x4(uint32_t& r0, uint32_t& r1, uint32_t& r2, uint32_t& r3,
                                        uint32_t addr) {
    asm volatile("ldmatrix.sync.aligned.m8n8.x4.shared.b16 {%0,%1,%2,%3}, [%4];"
                 : "=r"(r0), "=r"(r1), "=r"(r2), "=r"(r3) : "r"(addr));
}
__device__ __forceinline__ void mma_f16(float* c, const uint32_t* a, uint32_t b0, uint32_t b1) {
    asm volatile(
        "mma.sync.aligned.m16n8k16.row.col.f32.f16.f16.f32 "
        "{%0,%1,%2,%3}, {%4,%5,%6,%7}, {%8,%9}, {%0,%1,%2,%3};"
        : "+f"(c[0]), "+f"(c[1]), "+f"(c[2]), "+f"(c[3])
        : "r"(a[0]), "r"(a[1]), "r"(a[2]), "r"(a[3]), "r"(b0), "r"(b1));
}
#define SWZ128(o) ((o) ^ (((o) >> 3) & 0x70))

__device__ __forceinline__ uint32_t pack2h(float a, float b) {
    return (uint32_t)__half_as_ushort(__float2half_rn(a)) |
           ((uint32_t)__half_as_ushort(__float2half_rn(b)) << 16);
}

static constexpr int STAGE_BYTES = 32768;             // A 16KB + B 16KB
static constexpr int SMEM_BYTES  = 3 * STAGE_BYTES;   // 96KB -> 2 CTAs/SM

// ============================ shared GEMM mainloop ===========================
// 128 threads / 4 warps as 2(M) x 2(N); warp tile 64x64; CTA tile 128x128.
// 3-stage cp.async (prefetch distance 2, wait<=1 in steady state).
__device__ __forceinline__ void gemm_mainloop(
    float (&acc)[4][8][4], uint32_t sb,
    const __half* __restrict__ srcA, int lda,
    const __half* __restrict__ srcB, int ldb, int nch)
{
    const int tid = threadIdx.x, wid = tid >> 5, lane = tid & 31;
    const int warpM = (wid >> 1) * 64, warpN = (wid & 1) * 64;
    const int aRow  = warpM + (lane & 15);
    const int bRow  = warpN + (lane & 15);
    const int kHalf = (lane >> 4) * 8;

    auto load_stage = [&](int st, int k0) {
        const uint32_t stBase = sb + st * STAGE_BYTES;
#pragma unroll
        for (int i = 0; i < 8; i++) {
            const int idx = (i << 7) | tid;
            const int row = idx >> 3, k8 = (idx & 7) << 3;
            CP_ASYNC16(stBase + SWZ128((uint32_t)(row * 128 + k8 * 2)),
                       srcA + (long long)row * lda + k0 + k8);
        }
#pragma unroll
        for (int i = 0; i < 8; i++) {
            const int idx = (i << 7) | tid;
            const int row = idx >> 3, k8 = (idx & 7) << 3;
            CP_ASYNC16(stBase + 16384 + SWZ128((uint32_t)(row * 128 + k8 * 2)),
                       srcB + (long long)row * ldb + k0 + k8);
        }
    };

#pragma unroll
    for (int mi = 0; mi < 4; mi++)
#pragma unroll
        for (int ni = 0; ni < 8; ni++)
#pragma unroll
            for (int c = 0; c < 4; c++) acc[mi][ni][c] = 0.0f;

    load_stage(0, 0);
    CP_COMMIT();
    if (nch > 1) { load_stage(1, 64); CP_COMMIT(); }

    for (int i = 0; i < nch; i++) {
        const int st = i % 3;
        if (i + 1 < nch) CP_WAIT(1); else CP_WAIT(0);
        __syncthreads();
        if (i + 2 < nch) { load_stage((i + 2) % 3, (i + 2) << 6); CP_COMMIT(); }

        const uint32_t aB = sb + st * STAGE_BYTES;
        const uint32_t bB = aB + 16384;
#pragma unroll
        for (int ks = 0; ks < 4; ks++) {
            const int kb = (ks * 16 + kHalf) * 2;
            uint32_t bf[8][2];
#pragma unroll
            for (int np = 0; np < 4; np++) {
                uint32_t r0, r1, r2, r3;
                ldsm_x4(r0, r1, r2, r3, bB + SWZ128((uint32_t)((bRow + np * 16) * 128 + kb)));
                bf[np * 2 + 0][0] = r0; bf[np * 2 + 0][1] = r2;
                bf[np * 2 + 1][0] = r1; bf[np * 2 + 1][1] = r3;
            }
            uint32_t af[4][4];
#pragma unroll
            for (int mi = 0; mi < 4; mi++)
                ldsm_x4(af[mi][0], af[mi][1], af[mi][2], af[mi][3],
                        aB + SWZ128((uint32_t)((aRow + mi * 16) * 128 + kb)));
#pragma unroll
            for (int mi = 0; mi < 4; mi++)
#pragma unroll
                for (int ni = 0; ni < 8; ni++)
                    mma_f16(acc[mi][ni], af[mi], bf[ni][0], bf[ni][1]);
        }
    }
}

// ============================ prep kernels ===================================
__global__ __launch_bounds__(256) void halfXY_kernel(const float4* __restrict__ X,
                                                     const float4* __restrict__ Y) {
    int i = blockIdx.x * 256 + threadIdx.x;
    const float4* s; uint2* d; int j;
    if (i < 8388608) { s = X; d = (uint2*)g_Xh; j = i; }
    else             { s = Y; d = (uint2*)g_Yh; j = i - 8388608; }
    float4 v = s[j];
    uint2 hh;
    hh.x = pack2h(v.x, v.y);
    hh.y = pack2h(v.z, v.w);
    d[j] = hh;
}

__global__ __launch_bounds__(256) void prep2_kernel(const float* __restrict__ Wk,
                                                    const float* __restrict__ Wq,
                                                    const float* __restrict__ Wv,
                                                    const float* __restrict__ dag) {
    int i = blockIdx.x * 256 + threadIdx.x;
    if (i < 786432) {
        int z = i >> 18, r = i & 262143;
        const float* W = (z == 0) ? Wk : (z == 1) ? Wq : Wv;
        int hh = r >> 9, d = r & 511;
        g_Wth[i] = __float2half_rn(W[d * 512 + hh]);
    } else {
        int j = i - 786432;
        int t = j >> 10, s = j & 1023;
        g_dagU8[j] = (dag[s * 1024 + t] != 0.0f) ? 1 : 0;
    }
}

// ============================ projections (one launch) =======================
// grid (4, 512, 3): z=0 K (row-major), z=1 Q (row-major), z=2 V^T (transposed)
__global__ __launch_bounds__(128, 2) void proj_kernel(const float* __restrict__ bk,
                                                      const float* __restrict__ bq,
                                                      const float* __restrict__ bv)
{
    extern __shared__ char smem[];
    const int z = blockIdx.z;
    const __half* A = (z == 1) ? g_Yh : g_Xh;
    const __half* W = g_Wth + z * 262144;
    const float* bias = (z == 0) ? bk : (z == 1) ? bq : bv;
    __half* out = (z == 0) ? g_Kh : (z == 1) ? g_Qh : g_Vth;

    const int mBase = blockIdx.y * 128;
    const int nBase = blockIdx.x * 128;
    const int tid = threadIdx.x, wid = tid >> 5, lane = tid & 31;
    const int warpM = (wid >> 1) * 64, warpN = (wid & 1) * 64;
    const uint32_t sb = smem_u32(smem);

    float acc[4][8][4];
    gemm_mainloop(acc, sb, A + (long long)mBase * 512, 512,
                  W + (long long)nBase * 512, 512, 8);

    const int rBase = lane >> 2;
    const int cOff  = (lane & 3) * 2;

    if (z != 2) {
        // direct row-major fp16 stores
#pragma unroll
        for (int mi = 0; mi < 4; mi++)
#pragma unroll
            for (int ni = 0; ni < 8; ni++)
#pragma unroll
                for (int rh = 0; rh < 2; rh++) {
                    const int row = mBase + warpM + mi * 16 + rBase + rh * 8;
                    const int col = nBase + warpN + ni * 8 + cOff;
                    const float b0 = bias[col], b1 = bias[col + 1];
                    *(uint32_t*)(out + (long long)row * 512 + col) =
                        pack2h(acc[mi][ni][rh * 2] + b0, acc[mi][ni][rh * 2 + 1] + b1);
                }
    } else {
        // transposed output staged through smem (128 cols x 132 slots = 67.5KB)
        __syncthreads();
        uint32_t* stgU = (uint32_t*)smem;
#pragma unroll
        for (int mi = 0; mi < 4; mi++) {
            const int r0 = warpM + mi * 16 + rBase;
            const int r1 = r0 + 8;
#pragma unroll
            for (int ni = 0; ni < 8; ni++) {
                const int col = warpN + ni * 8 + cOff;
                const float b0 = bias[nBase + col], b1 = bias[nBase + col + 1];
                stgU[col * 132 + r0]       = (uint32_t)__half_as_ushort(__float2half_rn(acc[mi][ni][0] + b0));
                stgU[(col + 1) * 132 + r0] = (uint32_t)__half_as_ushort(__float2half_rn(acc[mi][ni][1] + b1));
                stgU[col * 132 + r1]       = (uint32_t)__half_as_ushort(__float2half_rn(acc[mi][ni][2] + b0));
                stgU[(col + 1) * 132 + r1] = (uint32_t)__half_as_ushort(__float2half_rn(acc[mi][ni][3] + b1));
            }
        }
        __syncthreads();
#pragma unroll
        for (int i = 0; i < 32; i++) {
            const int q = tid + i * 128;
            const int c = q >> 5, r4 = (q & 31) << 2;
            uint32_t w0 = stgU[c * 132 + r4], w1 = stgU[c * 132 + r4 + 1];
            uint32_t w2 = stgU[c * 132 + r4 + 2], w3 = stgU[c * 132 + r4 + 3];
            uint2 hh;
            hh.x = (w0 & 0xFFFF) | (w1 << 16);  hh.y = (w2 & 0xFFFF) | (w3 << 16);
            const int gt = mBase + r4;
            const int bat = gt >> 10, t0 = gt & 1023;
            const long long gi = ((long long)bat * 512 + (nBase + c)) * 1024 + t0;
            *(uint2*)(out + gi) = hh;
        }
    }
}

// ============================ scores + tile softmax ==========================
// grid (8, 8, 64), 128 thr. Direct E stores; per-(row,tile) stats for factor.
__global__ __launch_bounds__(128, 2) void scores_kernel()
{
    extern __shared__ char smem[];
    const int b = blockIdx.z;
    const int mBase = blockIdx.y * 128;     // t rows
    const int nBase = blockIdx.x * 128;     // s cols (tile = blockIdx.x)
    const int tid = threadIdx.x, wid = tid >> 5, lane = tid & 31;
    const int warpM = (wid >> 1) * 64, warpN = (wid & 1) * 64;
    const int ngrp = wid & 1;
    const uint32_t sb = smem_u32(smem);

    float acc[4][8][4];
    gemm_mainloop(acc, sb,
                  g_Qh + (long long)b * 524288 + (long long)mBase * 512, 512,
                  g_Kh + (long long)b * 524288 + (long long)nBase * 512, 512, 8);

    __syncthreads();                              // stages free for stats
    float* sm_mx = (float*)smem;                  // [2][128]
    float* sm_rs = (float*)(smem + 1024);         // [2][128]

    const int rBase = lane >> 2;
    const int cOff  = (lane & 3) * 2;
    const float scale = 0.044194173824159216f;    // 1/sqrt(512)

    float rmax[4][2];
#pragma unroll
    for (int mi = 0; mi < 4; mi++) { rmax[mi][0] = NEGV; rmax[mi][1] = NEGV; }
#pragma unroll
    for (int mi = 0; mi < 4; mi++)
#pragma unroll
        for (int ni = 0; ni < 8; ni++)
#pragma unroll
            for (int rh = 0; rh < 2; rh++) {
                const int t = mBase + warpM + mi * 16 + rBase + rh * 8;
                const int s = nBase + warpN + ni * 8 + cOff;
                const uint16_t dg = *(const uint16_t*)(g_dagU8 + (long long)t * 1024 + s);
                float v0 = acc[mi][ni][rh * 2]     * scale;
                float v1 = acc[mi][ni][rh * 2 + 1] * scale;
                v0 = ((dg & 0xFF) && v0 != 0.0f) ? v0 : NEGV;
                v1 = ((dg >> 8)  && v1 != 0.0f) ? v1 : NEGV;
                acc[mi][ni][rh * 2]     = v0;
                acc[mi][ni][rh * 2 + 1] = v1;
                rmax[mi][rh] = fmaxf(rmax[mi][rh], fmaxf(v0, v1));
            }
#pragma unroll
    for (int mi = 0; mi < 4; mi++)
#pragma unroll
        for (int rh = 0; rh < 2; rh++) {
            float v = rmax[mi][rh];
            v = fmaxf(v, __shfl_xor_sync(0xffffffffu, v, 1));
            v = fmaxf(v, __shfl_xor_sync(0xffffffffu, v, 2));
            if ((lane & 3) == 0)
                sm_mx[ngrp * 128 + warpM + mi * 16 + rBase + rh * 8] = v;
        }
    __syncthreads();

    float rsum[4][2] = {{0.f,0.f},{0.f,0.f},{0.f,0.f},{0.f,0.f}};
#pragma unroll
    for (int mi = 0; mi < 4; mi++)
#pragma unroll
        for (int rh = 0; rh < 2; rh++) {
            const int row = warpM + mi * 16 + rBase + rh * 8;
            const float mxt = fmaxf(sm_mx[row], sm_mx[128 + row]);
            const long long gbase = ((long long)b * 1024 + mBase + row) * 1024 + nBase;
#pragma unroll
            for (int ni = 0; ni < 8; ni++) {
                const int col = warpN + ni * 8 + cOff;
                float l0 = acc[mi][ni][rh * 2], l1 = acc[mi][ni][rh * 2 + 1];
                float e0 = (l0 < -1e29f) ? 0.0f : __expf(l0 - mxt);
                float e1 = (l1 < -1e29f) ? 0.0f : __expf(l1 - mxt);
                rsum[mi][rh] += e0 + e1;
                *(uint32_t*)(g_Ph + gbase + col) = pack2h(e0, e1);
            }
        }
#pragma unroll
    for (int mi = 0; mi < 4; mi++)
#pragma unroll
        for (int rh = 0; rh < 2; rh++) {
            float v = rsum[mi][rh];
            v += __shfl_xor_sync(0xffffffffu, v, 1);
            v += __shfl_xor_sync(0xffffffffu, v, 2);
            if ((lane & 3) == 0)
                sm_rs[ngrp * 128 + warpM + mi * 16 + rBase + rh * 8] = v;
        }
    __syncthreads();

    if (tid < 128) {
        const long long r = (long long)b * 1024 + mBase + tid;
        g_mxt[r * 8 + blockIdx.x] = fmaxf(sm_mx[tid], sm_mx[128 + tid]);
        g_rst[r * 8 + blockIdx.x] = sm_rs[tid] + sm_rs[128 + tid];
    }
}

// ============================ factor + scale =================================
__global__ __launch_bounds__(256) void factor_kernel() {
    const int r = blockIdx.x * 256 + threadIdx.x;
    float mx8[8], rs8[8];
#pragma unroll
    for (int j = 0; j < 8; j++) { mx8[j] = g_mxt[r * 8 + j]; rs8[j] = g_rst[r * 8 + j]; }
    float mx = mx8[0];
#pragma unroll
    for (int j = 1; j < 8; j++) mx = fmaxf(mx, mx8[j]);
    if (mx < -1e29f) {
#pragma unroll
        for (int j = 0; j < 8; j++) g_f[r * 8 + j] = 0.0f;
        return;
    }
    float l = 0.0f, a8[8];
#pragma unroll
    for (int j = 0; j < 8; j++) {
        a8[j] = (mx8[j] < -1e29f) ? 0.0f : __expf(mx8[j] - mx);
        l += rs8[j] * a8[j];
    }
    const float inv = 1.0f / l;
#pragma unroll
    for (int j = 0; j < 8; j++) g_f[r * 8 + j] = a8[j] * inv;
}

__global__ __launch_bounds__(256) void scale_kernel() {
    const int i = blockIdx.x * 256 + threadIdx.x;
    const int row = i >> 7;
    const int ti  = (i >> 4) & 7;
    const float f = g_f[row * 8 + ti];
    uint4* P = (uint4*)g_Ph;
    uint4 v = P[i];
    auto sc = [&](uint32_t w) -> uint32_t {
        float a = __half2float(__ushort_as_half((unsigned short)(w & 0xFFFF))) * f;
        float b = __half2float(__ushort_as_half((unsigned short)(w >> 16))) * f;
        return pack2h(a, b);
    };
    v.x = sc(v.x); v.y = sc(v.y); v.z = sc(v.z); v.w = sc(v.w);
    P[i] = v;
}

// ============================ A@V output =====================================
__global__ __launch_bounds__(128, 2) void av_kernel(float* __restrict__ O)
{
    extern __shared__ char smem[];
    const int b = blockIdx.z;
    const int mBase = blockIdx.y * 128;
    const int nBase = blockIdx.x * 128;
    const int tid = threadIdx.x, wid = tid >> 5, lane = tid & 31;
    const int warpM = (wid >> 1) * 64, warpN = (wid & 1) * 64;
    const uint32_t sb = smem_u32(smem);

    float acc[4][8][4];
    gemm_mainloop(acc, sb,
                  g_Ph  + (long long)b * 1048576 + (long long)mBase * 1024, 1024,
                  g_Vth + (long long)b * 524288  + (long long)nBase * 1024, 1024, 16);

    const int rBase = lane >> 2;
    const int cOff  = (lane & 3) * 2;
#pragma unroll
    for (int mi = 0; mi < 4; mi++)
#pragma unroll
        for (int ni = 0; ni < 8; ni++)
#pragma unroll
            for (int rh = 0; rh < 2; rh++) {
                const int row = mBase + warpM + mi * 16 + rBase + rh * 8;
                const int col = nBase + warpN + ni * 8 + cOff;
                float2 o;
                o.x = acc[mi][ni][rh * 2];
                o.y = acc[mi][ni][rh * 2 + 1];
                *(float2*)(O + (long long)b * 524288 + (long long)row * 512 + col) = o;
            }
}

// ============================ launch =========================================
extern "C" void kernel_launch(void* const* d_in, const int* in_sizes, int n_in,
                              void* d_out, int out_size)
{
    const float* X   = (const float*)d_in[0];
    const float* Y   = (const float*)d_in[1];
    const float* dag = (const float*)d_in[2];
    const float* Wk  = (const float*)d_in[3];
    const float* bk  = (const float*)d_in[4];
    const float* Wq  = (const float*)d_in[5];
    const float* bq  = (const float*)d_in[6];
    const float* Wv  = (const float*)d_in[7];
    const float* bv  = (const float*)d_in[8];
    float* O = (float*)d_out;

    cudaFuncSetAttribute(proj_kernel,   cudaFuncAttributeMaxDynamicSharedMemorySize, SMEM_BYTES);
    cudaFuncSetAttribute(scores_kernel, cudaFuncAttributeMaxDynamicSharedMemorySize, SMEM_BYTES);
    cudaFuncSetAttribute(av_kernel,     cudaFuncAttributeMaxDynamicSharedMemorySize, SMEM_BYTES);

    dim3 blk256(256), blk128(128);

    // prep
    halfXY_kernel<<<65536, blk256>>>((const float4*)X, (const float4*)Y);
    prep2_kernel<<<7168, blk256>>>(Wk, Wq, Wv, dag);

    // projections (K, Q, V^T) in one launch; 128x128 tiles, 128-thr CTAs
    dim3 gproj(4, 512, 3);
    proj_kernel<<<gproj, blk128, SMEM_BYTES>>>(bk, bq, bv);

    // scores + tile-local softmax pieces
    dim3 gsc(8, 8, 64);
    scores_kernel<<<gsc, blk128, SMEM_BYTES>>>();

    // combine stats -> per-tile scales; normalize E -> P (in place)
    factor_kernel<<<256, blk256>>>();
    scale_kernel<<<32768, blk256>>>();

    // output GEMM
    dim3 gav(4, 8, 64);
    av_kernel<<<gav, blk128, SMEM_BYTES>>>(O);
}